// round 13
// baseline (speedup 1.0000x reference)
#include <cuda_runtime.h>

// Problem constants (from reference setup_inputs)
#define Bc    4
#define Nc    16384
#define Kc    27
#define BNc   (Bc * Nc)            // 65536
#define Tc    (BNc * Kc)           // 1769472
#define BASEc 70
#define BASE3 343000               // 70^3
#define TABLE_SIZE (Bc * BASE3)    // 1372000
#define SHIFTc 3

#define NWORDS (Tc / 32)           // 55296 bitmask words (exact)
#define S1_BLOCKS (NWORDS / 256)   // 216 (exact)

#define GRID   888                 // 148 SMs x 6 CTAs — one resident wave
#define NTHR   (GRID * 256)        // 227328

// Scratch (__device__ globals; addresses formed only in device code — r7 lesson).
// 64-bit epoch-tagged table: value = (epoch<<32)|(Tc-1-t); atomicMax == min-t.
// Stale epochs lose automatically => NO per-call table init. Epoch is bumped
// at the END of each call by the kernel itself (after the last table read).
__device__ __align__(16) unsigned long long g_table[TABLE_SIZE];
__device__ int g_oi[TABLE_SIZE];                      // dense rank per key
__device__ int g_keybase[BNc];                        // encoded center key per point
__device__ __align__(16) unsigned g_bits[NWORDS];     // bit t set <=> first occurrence
__device__ int g_wordpre[NWORDS];                     // intra-tile exclusive popc prefix
__device__ int g_bsum2[S1_BLOCKS];                    // per-tile popc totals
__device__ int g_bpre2[S1_BLOCKS];                    // exclusive prefix of tile totals
__device__ int g_numout;                              // unique key count
__device__ unsigned g_epoch = 1;                      // call epoch (self-bumped)
__device__ int g_count = 0;                           // barrier arrivals (self-resetting)
__device__ volatile int g_sense = 0;                  // barrier sense (returns to 0 per call)
__device__ int g_cnt = 0;                             // scan1 completion counter (self-resetting)

// key delta per kernel offset k ('ij' meshgrid order)
__constant__ int c_delta[Kc] = {
    -4971, -4970, -4969,  -4901, -4900, -4899,  -4831, -4830, -4829,
      -71,   -70,   -69,     -1,     0,     1,     69,    70,    71,
     4829,  4830,  4831,   4899,  4900,  4901,   4969,  4970,  4971
};

// Sense-reversing grid barrier: self-resetting across calls (4 flips/call -> sense
// ends at 0; count reset by last arriver). All GRID blocks resident (one wave).
__device__ __forceinline__ void gsync(int& local_sense) {
    __syncthreads();
    if (threadIdx.x == 0) {
        int ls = local_sense ^ 1;
        local_sense = ls;
        __threadfence();
        if (atomicAdd(&g_count, 1) == GRID - 1) {
            g_count = 0;
            __threadfence();
            g_sense = ls;
        } else {
            while (g_sense != ls) __nanosleep(64);
        }
        __threadfence();
    }
    __syncthreads();
}

// zero any harness padding past 6T+1 (launched only when present)
__global__ void k_tail(float* __restrict__ p, long long n) {
    long long i = (long long)blockIdx.x * blockDim.x + threadIdx.x;
    long long stride = (long long)gridDim.x * blockDim.x;
    for (; i < n; i += stride) p[i] = 0.0f;
}

__global__ void __launch_bounds__(256, 6)
k_main(const int* __restrict__ coords, const int* __restrict__ batch,
       float* __restrict__ out) {
    const int gtid = blockIdx.x * 256 + threadIdx.x;
    const int tid  = threadIdx.x;
    const int lane = tid & 31, wid = tid >> 5;
    const unsigned ep = g_epoch;           // read ONCE at entry (bump happens post-barrier)
    int lsense = 0;
    __shared__ int wsum[8];
    __shared__ int sh[256];
    __shared__ int sh_pos;

    // ---- P1: zero bits + build (epoch-tagged atomicMax) ----
    if (gtid < NWORDS / 4)
        ((int4*)g_bits)[gtid] = make_int4(0, 0, 0, 0);
    for (int t = gtid; t < Tc; t += NTHR) {
        int idx = t / Kc;
        int k   = t - idx * Kc;
        int x = coords[idx * 3 + 0];
        int y = coords[idx * 3 + 1];
        int z = coords[idx * 3 + 2];
        int b = batch[idx];
        int kb = b * BASE3 + ((x + SHIFTc) * BASEc + (y + SHIFTc)) * BASEc + (z + SHIFTc);
        if (k == 0) g_keybase[idx] = kb;
        unsigned long long v = ((unsigned long long)ep << 32) | (unsigned)(Tc - 1 - t);
        atomicMax(&g_table[kb + c_delta[k]], v);
    }
    gsync(lsense);

    // ---- P2: bitset — 4 table entries per iteration ----
    for (int i = gtid; i < TABLE_SIZE / 4; i += NTHR) {
        ulonglong2 v0 = ((const ulonglong2*)g_table)[2 * i];
        ulonglong2 v1 = ((const ulonglong2*)g_table)[2 * i + 1];
#pragma unroll
        for (int j = 0; j < 4; j++) {
            unsigned long long v = (j < 2) ? ((j == 0) ? v0.x : v0.y)
                                           : ((j == 2) ? v1.x : v1.y);
            if ((unsigned)(v >> 32) == ep) {
                int ft = Tc - 1 - (int)(unsigned)v;
                atomicOr(&g_bits[ft >> 5], 1u << (ft & 31));
            }
        }
    }
    gsync(lsense);

    // ---- P3: scan1 (blocks 0..215) + last-done block does top scan inline ----
    if (blockIdx.x < S1_BLOCKS) {
        int w = blockIdx.x * 256 + tid;
        int c = __popc(g_bits[w]);
        int incl = c;
#pragma unroll
        for (int d = 1; d < 32; d <<= 1) {
            int v = __shfl_up_sync(0xffffffffu, incl, d);
            if (lane >= d) incl += v;
        }
        if (lane == 31) wsum[wid] = incl;
        __syncthreads();
        if (wid == 0) {
            int v = (lane < 8) ? wsum[lane] : 0;
#pragma unroll
            for (int d = 1; d < 8; d <<= 1) {
                int u = __shfl_up_sync(0xffffffffu, v, d);
                if (lane >= d) v += u;
            }
            if (lane < 8) wsum[lane] = v;
        }
        __syncthreads();
        g_wordpre[w] = ((wid == 0) ? 0 : wsum[wid - 1]) + incl - c;
        if (tid == 255) g_bsum2[blockIdx.x] = wsum[7];

        __threadfence();
        __syncthreads();
        if (tid == 0) sh_pos = atomicAdd(&g_cnt, 1);
        __syncthreads();
        if (sh_pos == S1_BLOCKS - 1) {
            if (tid == 0) g_cnt = 0;                  // rearm for next call
            int v = (tid < S1_BLOCKS) ? g_bsum2[tid] : 0;
            sh[tid] = v;
            __syncthreads();
#pragma unroll
            for (int d = 1; d < 256; d <<= 1) {
                int u = (tid >= d) ? sh[tid - d] : 0;
                __syncthreads();
                sh[tid] += u;
                __syncthreads();
            }
            if (tid < S1_BLOCKS) g_bpre2[tid] = sh[tid] - v;
            if (tid == S1_BLOCKS - 1) {
                g_numout = sh[tid];
                out[6LL * Tc] = (float)sh[tid];       // num_out
            }
        }
    }
    gsync(lsense);

    // ---- P4: assign rank per occupied key; write g_oi + out_key ----
    for (int i = gtid; i < TABLE_SIZE / 4; i += NTHR) {
        ulonglong2 v0 = ((const ulonglong2*)g_table)[2 * i];
        ulonglong2 v1 = ((const ulonglong2*)g_table)[2 * i + 1];
#pragma unroll
        for (int j = 0; j < 4; j++) {
            unsigned long long v = (j < 2) ? ((j == 0) ? v0.x : v0.y)
                                           : ((j == 2) ? v1.x : v1.y);
            if ((unsigned)(v >> 32) != ep) continue;
            int ft  = Tc - 1 - (int)(unsigned)v;
            int key = i * 4 + j;
            int w = ft >> 5;
            unsigned mask = (1u << (ft & 31)) - 1u;
            int rank = g_bpre2[w >> 8] + g_wordpre[w] + __popc(g_bits[w] & mask);
            g_oi[key] = rank;
            int rem = key % BASE3;
            int xx = rem / (BASEc * BASEc) - SHIFTc;
            int yy = (rem / BASEc) % BASEc - SHIFTc;
            int zz = rem % BASEc - SHIFTc;
            float* p = out + 3LL * Tc + 3LL * rank;
            p[0] = (float)xx; p[1] = (float)yy; p[2] = (float)zz;
        }
    }
    gsync(lsense);

    // Epoch bump for the NEXT call: safe — every block read g_epoch at entry,
    // and entry precedes this barrier; table is no longer read this call.
    if (blockIdx.x == 0 && tid == 0) g_epoch = ep + 1;

    // ---- P5: 8 t's per thread (single shot): in_idx/out_idx/rel_pos + padding ----
    int no = g_numout;
    int i = gtid;
    if (i < Tc / 8) {
        int t0 = i * 8;
        float va[8], vb[8], vc[8];
#pragma unroll
        for (int j = 0; j < 8; j++) {
            int t   = t0 + j;
            int idx = t / Kc;
            int k   = t - idx * Kc;
            int key = g_keybase[idx] + c_delta[k];
            va[j] = (float)(idx & (Nc - 1));
            vb[j] = (float)g_oi[key];
            vc[j] = (float)k;
        }
        float4* pa = (float4*)out;
        float4* pb = (float4*)(out + 1LL * Tc);
        float4* pc = (float4*)(out + 2LL * Tc);
        pa[2 * i]     = make_float4(va[0], va[1], va[2], va[3]);
        pa[2 * i + 1] = make_float4(va[4], va[5], va[6], va[7]);
        pb[2 * i]     = make_float4(vb[0], vb[1], vb[2], vb[3]);
        pb[2 * i + 1] = make_float4(vb[4], vb[5], vb[6], vb[7]);
        pc[2 * i]     = make_float4(vc[0], vc[1], vc[2], vc[3]);
        pc[2 * i + 1] = make_float4(vc[4], vc[5], vc[6], vc[7]);

        // out_key -1 padding for rows [num_out, Tc): rows t0..t0+7 <-> 6 float4
        if (t0 >= no) {
            float4 m1 = make_float4(-1.f, -1.f, -1.f, -1.f);
            float4* p = (float4*)(out + 3LL * Tc + 24LL * i);
#pragma unroll
            for (int j = 0; j < 6; j++) p[j] = m1;
        } else if (t0 + 7 >= no) {
#pragma unroll
            for (int j = 0; j < 8; j++) {
                int t = t0 + j;
                if (t >= no) {
                    float* p = out + 3LL * Tc + 3LL * t;
                    p[0] = -1.f; p[1] = -1.f; p[2] = -1.f;
                }
            }
        }
    }
}

extern "C" void kernel_launch(void* const* d_in, const int* in_sizes, int n_in,
                              void* d_out, int out_size) {
    // Identify inputs by SIZE: coordinates = [B,N,3] (3*BNc), batch = [B,N] (BNc).
    const int* coords = (const int*)d_in[0];
    const int* batch  = (const int*)d_in[n_in > 1 ? 1 : 0];
    for (int i = 0; i < n_in; i++) {
        if (in_sizes[i] == 3 * BNc) coords = (const int*)d_in[i];
        else if (in_sizes[i] == BNc) batch = (const int*)d_in[i];
    }
    float* out = (float*)d_out;
    long long osz = (long long)out_size;

    long long tail = osz - (6LL * Tc + 1);
    if (tail > 0) k_tail<<<512, 256>>>(out + 6LL * Tc + 1, tail);

    k_main<<<GRID, 256>>>(coords, batch, out);   // single self-contained launch
}

// round 14
// speedup vs baseline: 1.0850x; 1.0850x over previous
#include <cuda_runtime.h>

// Problem constants (from reference setup_inputs)
#define Bc    4
#define Nc    16384
#define Kc    27
#define BNc   (Bc * Nc)            // 65536
#define Tc    (BNc * Kc)           // 1769472
#define BASEc 70
#define BASE3 343000               // 70^3
#define TABLE_SIZE (Bc * BASE3)    // 1372000
#define SHIFTc 3

#define NWORDS (Tc / 32)           // 55296 bitmask words (exact)
#define S1_BLOCKS (NWORDS / 256)   // 216 (exact)

// Scratch (__device__ globals; addresses formed only in device code — r7 lesson).
// 64-bit epoch-tagged table: value = (epoch<<32)|(Tc-1-t); atomicMax == min-t.
// Stale epochs lose automatically => no per-call table init. Epoch bumped by
// k_out (stream-ordered after the last table reader, k_assign).
__device__ __align__(16) unsigned long long g_table[TABLE_SIZE];
__device__ int g_oi[TABLE_SIZE];                      // dense rank per key
__device__ int g_keybase[BNc];                        // encoded center key per point
__device__ __align__(16) unsigned g_bits[NWORDS];     // bit t set <=> first occurrence
__device__ int g_wordpre[NWORDS];                     // intra-tile exclusive popc prefix
__device__ int g_bsum2[S1_BLOCKS];                    // per-tile popc totals
__device__ int g_bpre2[S1_BLOCKS];                    // exclusive prefix of tile totals
__device__ int g_numout;                              // unique key count
__device__ unsigned g_epoch = 1;                      // call epoch (self-bumped in k_out)
__device__ int g_cnt = 0;                             // scan completion counter (self-resetting)

// key delta per kernel offset k ('ij' meshgrid order)
__constant__ int c_delta[Kc] = {
    -4971, -4970, -4969,  -4901, -4900, -4899,  -4831, -4830, -4829,
      -71,   -70,   -69,     -1,     0,     1,     69,    70,    71,
     4829,  4830,  4831,   4899,  4900,  4901,   4969,  4970,  4971
};

// zero any harness padding past 6T+1 (launched only when present)
__global__ void k_tail(float* __restrict__ p, long long n) {
    long long i = (long long)blockIdx.x * blockDim.x + threadIdx.x;
    long long stride = (long long)gridDim.x * blockDim.x;
    for (; i < n; i += stride) p[i] = 0.0f;
}

// One thread per (point, offset): epoch-tagged atomicMax; zero bits inline.
__global__ void k_build(const int* __restrict__ coords,
                        const int* __restrict__ batch) {
    int t = blockIdx.x * blockDim.x + threadIdx.x;
    if (t >= Tc) return;
    if (t < NWORDS) g_bits[t] = 0u;
    unsigned ep = g_epoch;
    int idx = t / Kc;
    int k   = t - idx * Kc;
    int x = coords[idx * 3 + 0];
    int y = coords[idx * 3 + 1];
    int z = coords[idx * 3 + 2];
    int b = batch[idx];
    int kb = b * BASE3 + ((x + SHIFTc) * BASEc + (y + SHIFTc)) * BASEc + (z + SHIFTc);
    if (k == 0) g_keybase[idx] = kb;
    unsigned long long v = ((unsigned long long)ep << 32) | (unsigned)(Tc - 1 - t);
    atomicMax(&g_table[kb + c_delta[k]], v);
}

// Table pass: occupied (this epoch) key -> set bit at its min-t.
__global__ void k_bitset() {
    int i = blockIdx.x * blockDim.x + threadIdx.x;
    if (i >= TABLE_SIZE / 4) return;
    unsigned ep = g_epoch;
    ulonglong2 v0 = ((const ulonglong2*)g_table)[2 * i];
    ulonglong2 v1 = ((const ulonglong2*)g_table)[2 * i + 1];
#pragma unroll
    for (int j = 0; j < 4; j++) {
        unsigned long long v = (j < 2) ? ((j == 0) ? v0.x : v0.y)
                                       : ((j == 2) ? v1.x : v1.y);
        if ((unsigned)(v >> 32) == ep) {
            int ft = Tc - 1 - (int)(unsigned)v;
            atomicOr(&g_bits[ft >> 5], 1u << (ft & 31));
        }
    }
}

// Scan: 216 blocks x 256 words; last-done block performs the 216-entry top scan.
__global__ void k_scan(float* __restrict__ out) {
    __shared__ int wsum[8];
    __shared__ int sh[256];
    __shared__ int sh_pos;
    int tid = threadIdx.x;
    int lane = tid & 31, wid = tid >> 5;
    int w = blockIdx.x * 256 + tid;
    int c = __popc(g_bits[w]);
    int incl = c;
#pragma unroll
    for (int d = 1; d < 32; d <<= 1) {
        int v = __shfl_up_sync(0xffffffffu, incl, d);
        if (lane >= d) incl += v;
    }
    if (lane == 31) wsum[wid] = incl;
    __syncthreads();
    if (wid == 0) {
        int v = (lane < 8) ? wsum[lane] : 0;
#pragma unroll
        for (int d = 1; d < 8; d <<= 1) {
            int u = __shfl_up_sync(0xffffffffu, v, d);
            if (lane >= d) v += u;
        }
        if (lane < 8) wsum[lane] = v;
    }
    __syncthreads();
    g_wordpre[w] = ((wid == 0) ? 0 : wsum[wid - 1]) + incl - c;
    if (tid == 255) g_bsum2[blockIdx.x] = wsum[7];

    __threadfence();
    __syncthreads();
    if (tid == 0) sh_pos = atomicAdd(&g_cnt, 1);
    __syncthreads();
    if (sh_pos == S1_BLOCKS - 1) {
        if (tid == 0) g_cnt = 0;                     // rearm for next call
        int v = (tid < S1_BLOCKS) ? g_bsum2[tid] : 0;
        sh[tid] = v;
        __syncthreads();
#pragma unroll
        for (int d = 1; d < 256; d <<= 1) {
            int u = (tid >= d) ? sh[tid - d] : 0;
            __syncthreads();
            sh[tid] += u;
            __syncthreads();
        }
        if (tid < S1_BLOCKS) g_bpre2[tid] = sh[tid] - v;
        if (tid == S1_BLOCKS - 1) {
            g_numout = sh[tid];
            out[6LL * Tc] = (float)sh[tid];          // num_out
        }
    }
}

// Table pass: occupied key -> rank via bitmask prefix; write g_oi + out_key.
__global__ void k_assign(float* __restrict__ out) {
    int i = blockIdx.x * blockDim.x + threadIdx.x;
    if (i >= TABLE_SIZE / 4) return;
    unsigned ep = g_epoch;
    ulonglong2 v0 = ((const ulonglong2*)g_table)[2 * i];
    ulonglong2 v1 = ((const ulonglong2*)g_table)[2 * i + 1];
#pragma unroll
    for (int j = 0; j < 4; j++) {
        unsigned long long v = (j < 2) ? ((j == 0) ? v0.x : v0.y)
                                       : ((j == 2) ? v1.x : v1.y);
        if ((unsigned)(v >> 32) != ep) continue;
        int ft  = Tc - 1 - (int)(unsigned)v;
        int key = i * 4 + j;
        int w = ft >> 5;
        unsigned mask = (1u << (ft & 31)) - 1u;
        int rank = g_bpre2[w >> 8] + g_wordpre[w] + __popc(g_bits[w] & mask);
        g_oi[key] = rank;
        int rem = key % BASE3;
        int xx = rem / (BASEc * BASEc) - SHIFTc;
        int yy = (rem / BASEc) % BASEc - SHIFTc;
        int zz = rem % BASEc - SHIFTc;
        float* p = out + 3LL * Tc + 3LL * rank;
        p[0] = (float)xx; p[1] = (float)yy; p[2] = (float)zz;
    }
}

// Final: 8 t's per thread: in_idx/out_idx/rel_pos (float4 x2 per stream) +
// out_key -1 padding for rows [num_out, Tc). Also bumps epoch for next call
// (safe: stream-ordered after k_assign, the last table reader; k_build of the
// next call is ordered after this kernel).
__global__ void k_out(float* __restrict__ out) {
    int i = blockIdx.x * blockDim.x + threadIdx.x;
    if (i == 0 && threadIdx.x == 0) g_epoch++;       // executes once (block 0 thread 0)
    if (i >= Tc / 8) return;
    int no = g_numout;
    int t0 = i * 8;
    float va[8], vb[8], vc[8];
#pragma unroll
    for (int j = 0; j < 8; j++) {
        int t   = t0 + j;
        int idx = t / Kc;
        int k   = t - idx * Kc;
        int key = g_keybase[idx] + c_delta[k];
        va[j] = (float)(idx & (Nc - 1));
        vb[j] = (float)g_oi[key];
        vc[j] = (float)k;
    }
    float4* pa = (float4*)out;
    float4* pb = (float4*)(out + 1LL * Tc);
    float4* pc = (float4*)(out + 2LL * Tc);
    pa[2 * i]     = make_float4(va[0], va[1], va[2], va[3]);
    pa[2 * i + 1] = make_float4(va[4], va[5], va[6], va[7]);
    pb[2 * i]     = make_float4(vb[0], vb[1], vb[2], vb[3]);
    pb[2 * i + 1] = make_float4(vb[4], vb[5], vb[6], vb[7]);
    pc[2 * i]     = make_float4(vc[0], vc[1], vc[2], vc[3]);
    pc[2 * i + 1] = make_float4(vc[4], vc[5], vc[6], vc[7]);

    if (t0 >= no) {                                  // fully padded: 6x float4
        float4 m1 = make_float4(-1.f, -1.f, -1.f, -1.f);
        float4* p = (float4*)(out + 3LL * Tc + 24LL * i);
#pragma unroll
        for (int j = 0; j < 6; j++) p[j] = m1;
    } else if (t0 + 7 >= no) {                       // boundary: scalar
#pragma unroll
        for (int j = 0; j < 8; j++) {
            int t = t0 + j;
            if (t >= no) {
                float* p = out + 3LL * Tc + 3LL * t;
                p[0] = -1.f; p[1] = -1.f; p[2] = -1.f;
            }
        }
    }
}

extern "C" void kernel_launch(void* const* d_in, const int* in_sizes, int n_in,
                              void* d_out, int out_size) {
    // Identify inputs by SIZE: coordinates = [B,N,3] (3*BNc), batch = [B,N] (BNc).
    const int* coords = (const int*)d_in[0];
    const int* batch  = (const int*)d_in[n_in > 1 ? 1 : 0];
    for (int i = 0; i < n_in; i++) {
        if (in_sizes[i] == 3 * BNc) coords = (const int*)d_in[i];
        else if (in_sizes[i] == BNc) batch = (const int*)d_in[i];
    }
    float* out = (float*)d_out;
    long long osz = (long long)out_size;

    long long tail = osz - (6LL * Tc + 1);
    if (tail > 0) k_tail<<<512, 256>>>(out + 6LL * Tc + 1, tail);

    k_build<<<(Tc + 255) / 256, 256>>>(coords, batch);
    k_bitset<<<(TABLE_SIZE / 4 + 255) / 256, 256>>>();
    k_scan<<<S1_BLOCKS, 256>>>(out);
    k_assign<<<(TABLE_SIZE / 4 + 255) / 256, 256>>>(out);
    k_out<<<(Tc / 8 + 255) / 256, 256>>>(out);
}